// round 7
// baseline (speedup 1.0000x reference)
#include <cuda_runtime.h>
#include <math.h>
#include <float.h>

#define Tn   512
#define Bn   64
#define En   256
#define Hn   512
#define G4   2048
#define NBLK 128
#define NTHR 256

// Scratch (device globals: the sanctioned alloc-free scratch mechanism)
__device__ float    g_xg[(size_t)Tn * G4 * Bn];  // [t][j][b]  256 MB
__device__ float    g_h[2][Hn * Bn];             // ping-pong, [hidx][b]
__device__ float    g_feat[Hn * Bn];             // [hidx][b]
__device__ unsigned g_count;                     // barrier arrivals (self-resetting)
__device__ unsigned g_gen;                       // barrier generation (free-running)

// Packed fp32x2 FMA (Blackwell sm_100+): two exact fp32 FMAs per FMA-pipe slot.
__device__ __forceinline__ unsigned long long ffma2(unsigned long long a,
                                                    unsigned long long b,
                                                    unsigned long long c) {
    unsigned long long d;
    asm("fma.rn.f32x2 %0, %1, %2, %3;" : "=l"(d) : "l"(a), "l"(b), "l"(c));
    return d;
}

// ---------------------------------------------------------------------------
// Grid-wide barrier (all NBLK blocks co-resident: 1 block/SM, NBLK <= SM count)
// ---------------------------------------------------------------------------
__device__ __forceinline__ void grid_barrier() {
    __syncthreads();
    if (threadIdx.x == 0) {
        volatile unsigned* genp = (volatile unsigned*)&g_gen;
        const unsigned cur = *genp;
        __threadfence();                            // release my step's writes
        if (atomicAdd(&g_count, 1u) == NBLK - 1) {
            g_count = 0u;
            __threadfence();
            *genp = cur + 1u;
        } else {
            while (*genp == cur) { __nanosleep(32); }
            __threadfence();                        // acquire
        }
    }
    __syncthreads();
}

// ---------------------------------------------------------------------------
// Kernel 1: fused embedding gather + input projection GEMM
//   xg[t][j][b] = sum_e emb[x[b,t]][e] * W_ih[j][e] + (b_ih[j] + b_hh[j])
// Grid: (16 j-tiles of 128, 512 t), block 256 threads, tile 128x64, BK=32.
// ---------------------------------------------------------------------------
__global__ __launch_bounds__(256)
void embed_gemm_kernel(const int*   __restrict__ x,
                       const float* __restrict__ emb,
                       const float* __restrict__ Wih,
                       const float* __restrict__ bih,
                       const float* __restrict__ bhh) {
    __shared__ float sW[32][132];   // [k][j], pad keeps float4 alignment
    __shared__ float sE[32][68];    // [k][b]
    __shared__ int   sTok[Bn];

    const int tid   = threadIdx.x;
    const int jBase = blockIdx.x * 128;
    const int t     = blockIdx.y;

    if (tid < Bn) sTok[tid] = x[tid * Tn + t];
    __syncthreads();

    const int tb = tid & 15;    // b-group (4 batches)
    const int tj = tid >> 4;    // j-group (8 rows)

    float acc[8][4];
#pragma unroll
    for (int jj = 0; jj < 8; ++jj)
#pragma unroll
        for (int bb = 0; bb < 4; ++bb) acc[jj][bb] = 0.f;

    for (int kc = 0; kc < En; kc += 32) {
#pragma unroll
        for (int i = 0; i < 16; ++i) {                 // 128x32 W chunk
            int idx = tid + i * 256;
            int k = idx & 31, j = idx >> 5;
            sW[k][j] = Wih[(size_t)(jBase + j) * En + kc + k];
        }
#pragma unroll
        for (int i = 0; i < 8; ++i) {                  // 64x32 emb chunk (gathered)
            int idx = tid + i * 256;
            int k = idx & 31, b = idx >> 5;
            sE[k][b] = emb[(size_t)sTok[b] * En + kc + k];
        }
        __syncthreads();

#pragma unroll
        for (int k = 0; k < 32; ++k) {
            const float4 ev = *reinterpret_cast<const float4*>(&sE[k][tb * 4]);
            const float4 wa = *reinterpret_cast<const float4*>(&sW[k][tj * 8]);
            const float4 wb = *reinterpret_cast<const float4*>(&sW[k][tj * 8 + 4]);
            const float e4[4] = {ev.x, ev.y, ev.z, ev.w};
            const float w8[8] = {wa.x, wa.y, wa.z, wa.w, wb.x, wb.y, wb.z, wb.w};
#pragma unroll
            for (int jj = 0; jj < 8; ++jj)
#pragma unroll
                for (int bb = 0; bb < 4; ++bb)
                    acc[jj][bb] += w8[jj] * e4[bb];
        }
        __syncthreads();
    }

    float* xg_t = g_xg + (size_t)t * (G4 * Bn);
#pragma unroll
    for (int jj = 0; jj < 8; ++jj) {
        const int j = jBase + tj * 8 + jj;
        const float bias = bih[j] + bhh[j];
        float4 v = make_float4(acc[jj][0] + bias, acc[jj][1] + bias,
                               acc[jj][2] + bias, acc[jj][3] + bias);
        *reinterpret_cast<float4*>(&xg_t[(size_t)j * Bn + tb * 4]) = v;
    }
}

// ---------------------------------------------------------------------------
// Kernel 2: persistent LSTM recurrence + ragged max-pool, f32x2 inner loop.
// Block p owns h indices [4p, 4p+4). W_hh rows are cached in smem with each
// weight DUPLICATED ({w,w}) so the inner loop is pure LDS.128 + fma.rn.f32x2:
// acc2[g][pair] += {w,w} * {h_b0,h_b1}. One grid barrier per step; h ping-pongs
// between two global buffers; cross-SM h traffic via __ldcg (L2-coherent).
// Dynamic smem: sH[512*64] + sW2[512*32] + sP[64*68] + sXg[16*64] = 213 KB
// ---------------------------------------------------------------------------
#define LSTM_SMEM ((Hn * Bn + Hn * 32 + 64 * 68 + 16 * Bn) * (int)sizeof(float))

__global__ __launch_bounds__(NTHR, 1)
void lstm_kernel(const float* __restrict__ Whh,
                 const int*   __restrict__ length) {
    extern __shared__ float sm[];
    float* sH  = sm;                   // [k][b]                  512*64
    float* sW2 = sH + Hn * Bn;         // [k][hh][g][dup2]        512*32
    float* sP  = sW2 + Hn * 32;        // [(ks,hl,g)][b pad 68]
    float* sXg = sP + 64 * 68;         // [(g,hl)][b]             16*64

    const int tid  = threadIdx.x;
    const int p    = blockIdx.x;
    const int hrow = p * 4;

    const int hl = tid & 3;            // dot-phase: local h index
    const int bg = (tid >> 2) & 15;    //            batch group (4)
    const int ks = tid >> 6;           //            k slice (128 wide)
    const int b0 = bg * 4;
    const int k0 = ks * 128;

    const int he = tid >> 6;           // epilogue: local h index (0..3)
    const int be = tid & 63;           //           batch (0..63)

    // Load this block's 16 W_hh rows, duplicated: sW2[k*32 + hh*8 + g*2 {+0,+1}]
#pragma unroll
    for (int r = 0; r < 16; ++r) {
        const int g = r & 3, hh = r >> 2;
        const float* src = Whh + (size_t)(g * Hn + hrow + hh) * Hn;
        for (int k = tid; k < Hn; k += NTHR) {
            const float v = src[k];
            sW2[k * 32 + hh * 8 + g * 2 + 0] = v;
            sW2[k * 32 + hh * 8 + g * 2 + 1] = v;
        }
    }
    // Zero this block's rows of h buffer 0 (fresh state every launch/replay).
    for (int i = tid; i < 4 * Bn; i += NTHR)
        g_h[0][hrow * Bn + i] = 0.f;

    float c_state = 0.f;
    float maxv    = -FLT_MAX;
    const int mylen = length[be];

    __threadfence();
    grid_barrier();

    for (int t = 0; t < Tn; ++t) {
        const float* hsrc = g_h[t & 1];
        float*       hdst = g_h[(t + 1) & 1];

        // Phase 1: stage full h[512][64] (L2-coherent loads) + xg slice.
        {
            const float4* s4 = (const float4*)hsrc;
            float4*       d4 = (float4*)sH;
#pragma unroll 8
            for (int i = tid; i < Hn * Bn / 4; i += NTHR) d4[i] = __ldcg(&s4[i]);
        }
        {
            const float* xg_t = g_xg + (size_t)t * (G4 * Bn);
#pragma unroll
            for (int i = tid; i < 16 * Bn; i += NTHR) {
                int b = i & 63, r = i >> 6;
                int g = r >> 2, hh = r & 3;
                sXg[i] = xg_t[(size_t)(g * Hn + hrow + hh) * Bn + b];
            }
        }
        __syncthreads();

        // Phase 2: partial dots over a 128-wide k slice, packed f32x2.
        // acc2[g][pr]: pr=0 -> batches (b0,b0+1), pr=1 -> (b0+2,b0+3)
        unsigned long long acc2[4][2];
#pragma unroll
        for (int g = 0; g < 4; ++g) { acc2[g][0] = 0ull; acc2[g][1] = 0ull; }
        {
            const float* pH = sH + k0 * Bn + b0;
            const float* pW = sW2 + k0 * 32 + hl * 8;
#pragma unroll 8
            for (int k = 0; k < 128; ++k) {
                const ulonglong2 h2 =
                    *reinterpret_cast<const ulonglong2*>(pH + k * Bn);
                const ulonglong2 wA =
                    *reinterpret_cast<const ulonglong2*>(pW + k * 32);
                const ulonglong2 wB =
                    *reinterpret_cast<const ulonglong2*>(pW + k * 32 + 4);
                acc2[0][0] = ffma2(wA.x, h2.x, acc2[0][0]);
                acc2[0][1] = ffma2(wA.x, h2.y, acc2[0][1]);
                acc2[1][0] = ffma2(wA.y, h2.x, acc2[1][0]);
                acc2[1][1] = ffma2(wA.y, h2.y, acc2[1][1]);
                acc2[2][0] = ffma2(wB.x, h2.x, acc2[2][0]);
                acc2[2][1] = ffma2(wB.x, h2.y, acc2[2][1]);
                acc2[3][0] = ffma2(wB.y, h2.x, acc2[3][0]);
                acc2[3][1] = ffma2(wB.y, h2.y, acc2[3][1]);
            }
        }
        {
            const int rbase = (ks * 4 + hl) * 4;
#pragma unroll
            for (int g = 0; g < 4; ++g) {
                ulonglong2 v; v.x = acc2[g][0]; v.y = acc2[g][1];
                *reinterpret_cast<ulonglong2*>(&sP[(rbase + g) * 68 + b0]) = v;
            }
        }
        __syncthreads();

        // Phase 3: epilogue — thread (he, be) owns one (h-index, batch) cell.
        {
            float gi = sXg[(0 * 4 + he) * 64 + be];
            float gf = sXg[(1 * 4 + he) * 64 + be];
            float gg = sXg[(2 * 4 + he) * 64 + be];
            float go = sXg[(3 * 4 + he) * 64 + be];
#pragma unroll
            for (int q = 0; q < 4; ++q) {
                const int rb = (q * 4 + he) * 4;
                gi += sP[(rb + 0) * 68 + be];
                gf += sP[(rb + 1) * 68 + be];
                gg += sP[(rb + 2) * 68 + be];
                go += sP[(rb + 3) * 68 + be];
            }
            const float is = 1.f / (1.f + __expf(-gi));
            const float fs = 1.f / (1.f + __expf(-gf));
            const float gt = tanhf(gg);
            const float os = 1.f / (1.f + __expf(-go));
            c_state = fs * c_state + is * gt;
            const float h = os * tanhf(c_state);
            hdst[(hrow + he) * Bn + be] = h;
            if (t < mylen) maxv = fmaxf(maxv, h);
        }
        grid_barrier();   // includes release fence for hdst writes
    }

    g_feat[(hrow + he) * Bn + be] = maxv;
}

// ---------------------------------------------------------------------------
// Kernel 3: classifier  out[b][c] = sum_h feat[h][b] * W_cls[c][h] + b_cls[c]
// ---------------------------------------------------------------------------
__global__ void cls_kernel(const float* __restrict__ Wcls,
                           const float* __restrict__ bcls,
                           float* __restrict__ out) {
    const int tid = threadIdx.x;   // 128 threads
    const int b = tid >> 1, c = tid & 1;
    float s = bcls[c];
#pragma unroll 8
    for (int h = 0; h < Hn; ++h)
        s += g_feat[h * Bn + b] * Wcls[c * Hn + h];
    out[b * 2 + c] = s;
}

// ---------------------------------------------------------------------------
extern "C" void kernel_launch(void* const* d_in, const int* in_sizes, int n_in,
                              void* d_out, int out_size) {
    const int*   x      = (const int*)  d_in[0];  // [64,512] int32
    const int*   length = (const int*)  d_in[1];  // [64,1]   int32
    const float* emb    = (const float*)d_in[2];  // [32000,256]
    const float* Wih    = (const float*)d_in[3];  // [2048,256]
    const float* Whh    = (const float*)d_in[4];  // [2048,512]
    const float* bih    = (const float*)d_in[5];  // [2048]
    const float* bhh    = (const float*)d_in[6];  // [2048]
    const float* Wcls   = (const float*)d_in[7];  // [2,512]
    const float* bcls   = (const float*)d_in[8];  // [2]
    float* out = (float*)d_out;                   // [64,2]

    cudaFuncSetAttribute(lstm_kernel,
                         cudaFuncAttributeMaxDynamicSharedMemorySize, LSTM_SMEM);

    embed_gemm_kernel<<<dim3(16, Tn), 256>>>(x, emb, Wih, bih, bhh);
    lstm_kernel<<<NBLK, NTHR, LSTM_SMEM>>>(Whh, length);
    cls_kernel<<<1, 128>>>(Wcls, bcls, out);
    (void)in_sizes; (void)n_in; (void)out_size;
}

// round 8
// speedup vs baseline: 1.0979x; 1.0979x over previous
#include <cuda_runtime.h>
#include <math.h>
#include <float.h>

#define Tn   512
#define Bn   64
#define En   256
#define Hn   512
#define G4   2048
#define NBLK 128
#define NTHR 256

// Scratch (device globals: the sanctioned alloc-free scratch mechanism)
__device__ float    g_xg[(size_t)Tn * G4 * Bn];  // [t][j][b]  256 MB
__device__ float    g_h[2][Hn * Bn];             // ping-pong, [hidx][b]
__device__ float    g_feat[Hn * Bn];             // [hidx][b]
__device__ unsigned g_count;                     // barrier arrivals (self-resetting)
__device__ unsigned g_gen;                       // barrier generation (free-running)

// ---------------------------------------------------------------------------
// Scoped memory ops (all cross-SM data traffic is L2-scoped: STG + cp.async.cg,
// so gpu-scope acquire/release suffices — no full MEMBAR / L1 flush needed).
// ---------------------------------------------------------------------------
__device__ __forceinline__ unsigned ld_relaxed_gpu(const unsigned* p) {
    unsigned v;
    asm volatile("ld.relaxed.gpu.global.u32 %0, [%1];" : "=r"(v) : "l"(p));
    return v;
}
__device__ __forceinline__ unsigned ld_acquire_gpu(const unsigned* p) {
    unsigned v;
    asm volatile("ld.acquire.gpu.global.u32 %0, [%1];" : "=r"(v) : "l"(p));
    return v;
}
__device__ __forceinline__ unsigned atom_add_release_gpu(unsigned* p, unsigned v) {
    unsigned old;
    asm volatile("atom.add.release.gpu.global.u32 %0, [%1], %2;"
                 : "=r"(old) : "l"(p), "r"(v));
    return old;
}
__device__ __forceinline__ void st_relaxed_gpu(unsigned* p, unsigned v) {
    asm volatile("st.relaxed.gpu.global.u32 [%0], %1;" :: "l"(p), "r"(v));
}
__device__ __forceinline__ void st_release_gpu(unsigned* p, unsigned v) {
    asm volatile("st.release.gpu.global.u32 [%0], %1;" :: "l"(p), "r"(v));
}

__device__ __forceinline__ void cp_async16(void* s, const void* g) {
    unsigned saddr = (unsigned)__cvta_generic_to_shared(s);
    asm volatile("cp.async.cg.shared.global [%0], [%1], 16;"
                 :: "r"(saddr), "l"(g));
}
#define CP_COMMIT() asm volatile("cp.async.commit_group;")
#define CP_WAIT(N)  asm volatile("cp.async.wait_group %0;" :: "n"(N))

// ---------------------------------------------------------------------------
// Grid-wide generation barrier, scoped-atomic version (no full fences).
// All NBLK blocks co-resident (1 block/SM, NBLK <= SM count).
// ---------------------------------------------------------------------------
__device__ __forceinline__ void grid_barrier() {
    __syncthreads();
    if (threadIdx.x == 0) {
        const unsigned cur = ld_relaxed_gpu(&g_gen);
        if (atom_add_release_gpu(&g_count, 1u) == NBLK - 1) {
            st_relaxed_gpu(&g_count, 0u);
            st_release_gpu(&g_gen, cur + 1u);   // release orders the reset too
        } else {
            while (ld_acquire_gpu(&g_gen) == cur) { __nanosleep(32); }
        }
    }
    __syncthreads();
}

// ---------------------------------------------------------------------------
// Kernel 1: fused embedding gather + input projection GEMM
//   xg[t][j][b] = sum_e emb[x[b,t]][e] * W_ih[j][e] + (b_ih[j] + b_hh[j])
// Grid: (16 j-tiles of 128, 512 t), block 256 threads, tile 128x64, BK=32.
// ---------------------------------------------------------------------------
__global__ __launch_bounds__(256)
void embed_gemm_kernel(const int*   __restrict__ x,
                       const float* __restrict__ emb,
                       const float* __restrict__ Wih,
                       const float* __restrict__ bih,
                       const float* __restrict__ bhh) {
    __shared__ float sW[32][132];   // [k][j], pad keeps float4 alignment
    __shared__ float sE[32][68];    // [k][b]
    __shared__ int   sTok[Bn];

    const int tid   = threadIdx.x;
    const int jBase = blockIdx.x * 128;
    const int t     = blockIdx.y;

    if (tid < Bn) sTok[tid] = x[tid * Tn + t];
    __syncthreads();

    const int tb = tid & 15;    // b-group (4 batches)
    const int tj = tid >> 4;    // j-group (8 rows)

    float acc[8][4];
#pragma unroll
    for (int jj = 0; jj < 8; ++jj)
#pragma unroll
        for (int bb = 0; bb < 4; ++bb) acc[jj][bb] = 0.f;

    for (int kc = 0; kc < En; kc += 32) {
#pragma unroll
        for (int i = 0; i < 16; ++i) {                 // 128x32 W chunk
            int idx = tid + i * 256;
            int k = idx & 31, j = idx >> 5;
            sW[k][j] = Wih[(size_t)(jBase + j) * En + kc + k];
        }
#pragma unroll
        for (int i = 0; i < 8; ++i) {                  // 64x32 emb chunk (gathered)
            int idx = tid + i * 256;
            int k = idx & 31, b = idx >> 5;
            sE[k][b] = emb[(size_t)sTok[b] * En + kc + k];
        }
        __syncthreads();

#pragma unroll
        for (int k = 0; k < 32; ++k) {
            const float4 ev = *reinterpret_cast<const float4*>(&sE[k][tb * 4]);
            const float4 wa = *reinterpret_cast<const float4*>(&sW[k][tj * 8]);
            const float4 wb = *reinterpret_cast<const float4*>(&sW[k][tj * 8 + 4]);
            const float e4[4] = {ev.x, ev.y, ev.z, ev.w};
            const float w8[8] = {wa.x, wa.y, wa.z, wa.w, wb.x, wb.y, wb.z, wb.w};
#pragma unroll
            for (int jj = 0; jj < 8; ++jj)
#pragma unroll
                for (int bb = 0; bb < 4; ++bb)
                    acc[jj][bb] += w8[jj] * e4[bb];
        }
        __syncthreads();
    }

    float* xg_t = g_xg + (size_t)t * (G4 * Bn);
#pragma unroll
    for (int jj = 0; jj < 8; ++jj) {
        const int j = jBase + tj * 8 + jj;
        const float bias = bih[j] + bhh[j];
        float4 v = make_float4(acc[jj][0] + bias, acc[jj][1] + bias,
                               acc[jj][2] + bias, acc[jj][3] + bias);
        *reinterpret_cast<float4*>(&xg_t[(size_t)j * Bn + tb * 4]) = v;
    }
}

// ---------------------------------------------------------------------------
// Kernel 2: persistent LSTM recurrence + ragged max-pool.
// Block p owns h indices [4p,4p+4). Thread = (hh in 0..3, b in 0..63) owns all
// K=512 for its 4 gate accumulators -> register-local epilogue, no partial-sum
// smem round-trip. h[512][64] staged per step via cp.async.cg in 4 k-chunks of
// 128, software-pipelined against the dot. xg[t+1] is prefetched from DRAM
// during step t (double buffer). One scoped grid barrier per step; h ping-pongs
// between two global buffers (all cross-SM traffic is L2-scoped).
// Dynamic smem: sH[512*64] + sW[512*16] + sXg[2][16*64] = 168 KB
// ---------------------------------------------------------------------------
#define LSTM_SMEM ((Hn * Bn + Hn * 16 + 2 * 16 * Bn) * (int)sizeof(float))

__global__ __launch_bounds__(NTHR, 1)
void lstm_kernel(const float* __restrict__ Whh,
                 const int*   __restrict__ length) {
    extern __shared__ float sm[];
    float* sH  = sm;                   // [k][b]           512*64
    float* sW  = sH + Hn * Bn;         // [k][hh*4+g]      512*16
    float* sXg = sW + Hn * 16;         // [2][r=g*4+hh][b] 2*16*64

    const int tid  = threadIdx.x;
    const int p    = blockIdx.x;
    const int hrow = p * 4;

    const int hh = tid >> 6;           // local h index (0..3)
    const int b  = tid & 63;           // batch (0..63)

    // Load this block's 16 W_hh rows: sW[k*16 + hh*4 + g]
#pragma unroll
    for (int r = 0; r < 16; ++r) {
        const int g = r & 3, h2 = r >> 2;
        const float* src = Whh + (size_t)(g * Hn + hrow + h2) * Hn;
        for (int k = tid; k < Hn; k += NTHR)
            sW[k * 16 + h2 * 4 + g] = src[k];
    }
    // Zero this block's rows of h buffer 0 (fresh state every launch/replay).
    for (int i = tid; i < 4 * Bn; i += NTHR)
        g_h[0][hrow * Bn + i] = 0.f;

    // Prefetch xg slice for t=0 (1 cp.async group left pending into the loop).
    {
        const int r = tid >> 4, seg = tid & 15;     // 16 rows x 16 segs
        const int g = r >> 2, h2 = r & 3;
        const float* src = g_xg + (size_t)(g * Hn + hrow + h2) * Bn + seg * 4;
        cp_async16(&sXg[r * 64 + seg * 4], src);
        CP_COMMIT();
    }

    float c_state = 0.f;
    float maxv    = -FLT_MAX;
    const int mylen = length[b];
    float acc0, acc1, acc2, acc3;

    grid_barrier();   // release covers the h-buffer zeroing

    for (int t = 0; t < Tn; ++t) {
        const float* hsrc = g_h[t & 1];
        float*       hdst = g_h[(t + 1) & 1];
        const float* xgCur = sXg + (t & 1) * (16 * Bn);
        float*       xgNxt = sXg + ((t + 1) & 1) * (16 * Bn);

        // Issue: 4 h-chunk groups (32 KB each) + xg[t+1] prefetch group.
#pragma unroll
        for (int c = 0; c < 4; ++c) {
            const float* gsrc = hsrc + c * (128 * Bn);
            float*       sdst = sH   + c * (128 * Bn);
#pragma unroll
            for (int j = 0; j < 8; ++j) {
                const int i = tid + j * NTHR;       // 2048 16B segs / chunk
                cp_async16(sdst + i * 4, gsrc + i * 4);
            }
            CP_COMMIT();
        }
        {
            const int tn = (t + 1 < Tn) ? t + 1 : t;
            const int r = tid >> 4, seg = tid & 15;
            const int g = r >> 2, h2 = r & 3;
            const float* src = g_xg + (size_t)tn * (G4 * Bn)
                             + (size_t)(g * Hn + hrow + h2) * Bn + seg * 4;
            cp_async16(xgNxt + r * 64 + seg * 4, src);
            CP_COMMIT();
        }

        acc0 = acc1 = acc2 = acc3 = 0.f;

        // Pipelined dot: wait chunk c (+ xg[t] on c=0), then FMA over it.
#pragma unroll
        for (int c = 0; c < 4; ++c) {
            if (c == 0)      { CP_WAIT(4); }   // retires xg[t] + chunk0
            else if (c == 1) { CP_WAIT(3); }
            else if (c == 2) { CP_WAIT(2); }
            else             { CP_WAIT(1); }   // leaves xg[t+1] pending
            __syncthreads();

            const float* pH = sH + c * (128 * Bn) + b;
            const float* pW = sW + c * (128 * 16) + hh * 4;
#pragma unroll 8
            for (int k = 0; k < 128; ++k) {
                const float  hk = pH[k * Bn];                       // coalesced
                const float4 w  = *reinterpret_cast<const float4*>(pW + k * 16); // bcast
                acc0 += w.x * hk;
                acc1 += w.y * hk;
                acc2 += w.z * hk;
                acc3 += w.w * hk;
            }
        }

        // Epilogue: fully register-local (gate order i,f,g,o).
        {
            const float gi = xgCur[(0 * 4 + hh) * 64 + b] + acc0;
            const float gf = xgCur[(1 * 4 + hh) * 64 + b] + acc1;
            const float gg = xgCur[(2 * 4 + hh) * 64 + b] + acc2;
            const float go = xgCur[(3 * 4 + hh) * 64 + b] + acc3;
            const float is = 1.f / (1.f + __expf(-gi));
            const float fs = 1.f / (1.f + __expf(-gf));
            const float gt = tanhf(gg);
            const float os = 1.f / (1.f + __expf(-go));
            c_state = fs * c_state + is * gt;
            const float h = os * tanhf(c_state);
            hdst[(hrow + hh) * Bn + b] = h;
            if (t < mylen) maxv = fmaxf(maxv, h);
        }
        grid_barrier();   // release-arrive orders the h store
    }

    g_feat[(hrow + hh) * Bn + b] = maxv;
}

// ---------------------------------------------------------------------------
// Kernel 3: classifier  out[b][c] = sum_h feat[h][b] * W_cls[c][h] + b_cls[c]
// ---------------------------------------------------------------------------
__global__ void cls_kernel(const float* __restrict__ Wcls,
                           const float* __restrict__ bcls,
                           float* __restrict__ out) {
    const int tid = threadIdx.x;   // 128 threads
    const int b = tid >> 1, c = tid & 1;
    float s = bcls[c];
#pragma unroll 8
    for (int h = 0; h < Hn; ++h)
        s += g_feat[h * Bn + b] * Wcls[c * Hn + h];
    out[b * 2 + c] = s;
}

// ---------------------------------------------------------------------------
extern "C" void kernel_launch(void* const* d_in, const int* in_sizes, int n_in,
                              void* d_out, int out_size) {
    const int*   x      = (const int*)  d_in[0];  // [64,512] int32
    const int*   length = (const int*)  d_in[1];  // [64,1]   int32
    const float* emb    = (const float*)d_in[2];  // [32000,256]
    const float* Wih    = (const float*)d_in[3];  // [2048,256]
    const float* Whh    = (const float*)d_in[4];  // [2048,512]
    const float* bih    = (const float*)d_in[5];  // [2048]
    const float* bhh    = (const float*)d_in[6];  // [2048]
    const float* Wcls   = (const float*)d_in[7];  // [2,512]
    const float* bcls   = (const float*)d_in[8];  // [2]
    float* out = (float*)d_out;                   // [64,2]

    cudaFuncSetAttribute(lstm_kernel,
                         cudaFuncAttributeMaxDynamicSharedMemorySize, LSTM_SMEM);

    embed_gemm_kernel<<<dim3(16, Tn), 256>>>(x, emb, Wih, bih, bhh);
    lstm_kernel<<<NBLK, NTHR, LSTM_SMEM>>>(Whh, length);
    cls_kernel<<<1, 128>>>(Wcls, bcls, out);
    (void)in_sizes; (void)n_in; (void)out_size;
}

// round 9
// speedup vs baseline: 1.1040x; 1.0055x over previous
#include <cuda_runtime.h>
#include <math.h>
#include <float.h>

#define Tn   512
#define Bn   64
#define En   256
#define Hn   512
#define G4   2048
#define NBLK 128
#define NTHR 256

// Scratch (device globals: the sanctioned alloc-free scratch mechanism)
__device__ float    g_xg[(size_t)Tn * G4 * Bn];  // [t][j][b]  256 MB
__device__ float    g_h[2][Hn * Bn];             // ping-pong, [hidx][b]
__device__ float    g_feat[Hn * Bn];             // [hidx][b]
__device__ unsigned g_count;                     // barrier arrivals (self-resetting)
__device__ unsigned g_gen;                       // barrier generation (free-running)

// ---------------------------------------------------------------------------
// Scoped memory ops (all cross-SM data traffic is L2-scoped: STG + cp.async.cg,
// so gpu-scope acquire/release suffices — no full MEMBAR / L1 flush needed).
// ---------------------------------------------------------------------------
__device__ __forceinline__ unsigned ld_relaxed_gpu(const unsigned* p) {
    unsigned v;
    asm volatile("ld.relaxed.gpu.global.u32 %0, [%1];" : "=r"(v) : "l"(p));
    return v;
}
__device__ __forceinline__ unsigned ld_acquire_gpu(const unsigned* p) {
    unsigned v;
    asm volatile("ld.acquire.gpu.global.u32 %0, [%1];" : "=r"(v) : "l"(p));
    return v;
}
__device__ __forceinline__ unsigned atom_add_release_gpu(unsigned* p, unsigned v) {
    unsigned old;
    asm volatile("atom.add.release.gpu.global.u32 %0, [%1], %2;"
                 : "=r"(old) : "l"(p), "r"(v));
    return old;
}
__device__ __forceinline__ void st_relaxed_gpu(unsigned* p, unsigned v) {
    asm volatile("st.relaxed.gpu.global.u32 [%0], %1;" :: "l"(p), "r"(v));
}
__device__ __forceinline__ void st_release_gpu(unsigned* p, unsigned v) {
    asm volatile("st.release.gpu.global.u32 [%0], %1;" :: "l"(p), "r"(v));
}

__device__ __forceinline__ void cp_async16(void* s, const void* g) {
    unsigned saddr = (unsigned)__cvta_generic_to_shared(s);
    asm volatile("cp.async.cg.shared.global [%0], [%1], 16;"
                 :: "r"(saddr), "l"(g));
}
#define CP_COMMIT() asm volatile("cp.async.commit_group;")
#define CP_WAIT(N)  asm volatile("cp.async.wait_group %0;" :: "n"(N))

// Packed fp32x2 FMA (exact fp32 semantics, 2 MACs per FMA-pipe slot).
__device__ __forceinline__ unsigned long long ffma2(unsigned long long a,
                                                    unsigned long long b,
                                                    unsigned long long c) {
    unsigned long long d;
    asm("fma.rn.f32x2 %0, %1, %2, %3;" : "=l"(d) : "l"(a), "l"(b), "l"(c));
    return d;
}

// Fast, accurate-enough transcendentals (MUFU-based, ~1e-7 rel err).
__device__ __forceinline__ float sigf(float x) {
    return 1.f / (1.f + __expf(-x));
}
__device__ __forceinline__ float tanhf_fast(float x) {
    return 2.f / (1.f + __expf(-2.f * x)) - 1.f;
}

// ---------------------------------------------------------------------------
// Grid-wide generation barrier, scoped-atomic version. Busy acquire-poll
// (no nanosleep: detection latency ~1 L2 RT; 127 read-shared polls are cheap).
// ---------------------------------------------------------------------------
__device__ __forceinline__ void grid_barrier() {
    __syncthreads();
    if (threadIdx.x == 0) {
        const unsigned cur = ld_relaxed_gpu(&g_gen);
        if (atom_add_release_gpu(&g_count, 1u) == NBLK - 1) {
            st_relaxed_gpu(&g_count, 0u);
            st_release_gpu(&g_gen, cur + 1u);   // release orders the reset too
        } else {
            while (ld_acquire_gpu(&g_gen) == cur) {}
        }
    }
    __syncthreads();
}

// ---------------------------------------------------------------------------
// Kernel 1: fused embedding gather + input projection GEMM
//   xg[t][j][b] = sum_e emb[x[b,t]][e] * W_ih[j][e] + (b_ih[j] + b_hh[j])
// Grid: (16 j-tiles of 128, 512 t), block 256 threads, tile 128x64, BK=32.
// ---------------------------------------------------------------------------
__global__ __launch_bounds__(256)
void embed_gemm_kernel(const int*   __restrict__ x,
                       const float* __restrict__ emb,
                       const float* __restrict__ Wih,
                       const float* __restrict__ bih,
                       const float* __restrict__ bhh) {
    __shared__ float sW[32][132];   // [k][j], pad keeps float4 alignment
    __shared__ float sE[32][68];    // [k][b]
    __shared__ int   sTok[Bn];

    const int tid   = threadIdx.x;
    const int jBase = blockIdx.x * 128;
    const int t     = blockIdx.y;

    if (tid < Bn) sTok[tid] = x[tid * Tn + t];
    __syncthreads();

    const int tb = tid & 15;    // b-group (4 batches)
    const int tj = tid >> 4;    // j-group (8 rows)

    float acc[8][4];
#pragma unroll
    for (int jj = 0; jj < 8; ++jj)
#pragma unroll
        for (int bb = 0; bb < 4; ++bb) acc[jj][bb] = 0.f;

    for (int kc = 0; kc < En; kc += 32) {
#pragma unroll
        for (int i = 0; i < 16; ++i) {                 // 128x32 W chunk
            int idx = tid + i * 256;
            int k = idx & 31, j = idx >> 5;
            sW[k][j] = Wih[(size_t)(jBase + j) * En + kc + k];
        }
#pragma unroll
        for (int i = 0; i < 8; ++i) {                  // 64x32 emb chunk (gathered)
            int idx = tid + i * 256;
            int k = idx & 31, b = idx >> 5;
            sE[k][b] = emb[(size_t)sTok[b] * En + kc + k];
        }
        __syncthreads();

#pragma unroll
        for (int k = 0; k < 32; ++k) {
            const float4 ev = *reinterpret_cast<const float4*>(&sE[k][tb * 4]);
            const float4 wa = *reinterpret_cast<const float4*>(&sW[k][tj * 8]);
            const float4 wb = *reinterpret_cast<const float4*>(&sW[k][tj * 8 + 4]);
            const float e4[4] = {ev.x, ev.y, ev.z, ev.w};
            const float w8[8] = {wa.x, wa.y, wa.z, wa.w, wb.x, wb.y, wb.z, wb.w};
#pragma unroll
            for (int jj = 0; jj < 8; ++jj)
#pragma unroll
                for (int bb = 0; bb < 4; ++bb)
                    acc[jj][bb] += w8[jj] * e4[bb];
        }
        __syncthreads();
    }

    float* xg_t = g_xg + (size_t)t * (G4 * Bn);
#pragma unroll
    for (int jj = 0; jj < 8; ++jj) {
        const int j = jBase + tj * 8 + jj;
        const float bias = bih[j] + bhh[j];
        float4 v = make_float4(acc[jj][0] + bias, acc[jj][1] + bias,
                               acc[jj][2] + bias, acc[jj][3] + bias);
        *reinterpret_cast<float4*>(&xg_t[(size_t)j * Bn + tb * 4]) = v;
    }
}

// ---------------------------------------------------------------------------
// Kernel 2: persistent LSTM recurrence + ragged max-pool, f32x2 dot.
// Block p owns h indices [4p,4p+4). Thread = (hh, b) owns all K=512 for its 4
// gates as two packed f32x2 accumulators {i,f},{g,o}: per k it's
// LDS.32 hk + pack + LDS.128 w4 + 2 FFMA2. h staged per step via cp.async.cg
// in 4 pipelined k-chunks; xg[t+1] prefetched during step t. One scoped grid
// barrier per step; h ping-pongs between two global buffers.
// Dynamic smem: sH[512*64] + sW[512*16] + sXg[2][16*64] = 168 KB
// ---------------------------------------------------------------------------
#define LSTM_SMEM ((Hn * Bn + Hn * 16 + 2 * 16 * Bn) * (int)sizeof(float))

__global__ __launch_bounds__(NTHR, 1)
void lstm_kernel(const float* __restrict__ Whh,
                 const int*   __restrict__ length) {
    extern __shared__ float sm[];
    float* sH  = sm;                   // [k][b]           512*64
    float* sW  = sH + Hn * Bn;         // [k][hh*4+g]      512*16
    float* sXg = sW + Hn * 16;         // [2][r=g*4+hh][b] 2*16*64

    const int tid  = threadIdx.x;
    const int p    = blockIdx.x;
    const int hrow = p * 4;

    const int hh = tid >> 6;           // local h index (0..3)
    const int b  = tid & 63;           // batch (0..63)

    // Load this block's 16 W_hh rows: sW[k*16 + hh*4 + g], gate order i,f,g,o.
#pragma unroll
    for (int r = 0; r < 16; ++r) {
        const int g = r & 3, h2 = r >> 2;
        const float* src = Whh + (size_t)(g * Hn + hrow + h2) * Hn;
        for (int k = tid; k < Hn; k += NTHR)
            sW[k * 16 + h2 * 4 + g] = src[k];
    }
    // Zero this block's rows of h buffer 0 (fresh state every launch/replay).
    for (int i = tid; i < 4 * Bn; i += NTHR)
        g_h[0][hrow * Bn + i] = 0.f;

    // Prefetch xg slice for t=0 (1 cp.async group left pending into the loop).
    {
        const int r = tid >> 4, seg = tid & 15;     // 16 rows x 16 segs
        const int g = r >> 2, h2 = r & 3;
        const float* src = g_xg + (size_t)(g * Hn + hrow + h2) * Bn + seg * 4;
        cp_async16(&sXg[r * 64 + seg * 4], src);
        CP_COMMIT();
    }

    float c_state = 0.f;
    float maxv    = -FLT_MAX;
    const int mylen = length[b];

    grid_barrier();   // release covers the h-buffer zeroing

    for (int t = 0; t < Tn; ++t) {
        const float* hsrc = g_h[t & 1];
        float*       hdst = g_h[(t + 1) & 1];
        const float* xgCur = sXg + (t & 1) * (16 * Bn);
        float*       xgNxt = sXg + ((t + 1) & 1) * (16 * Bn);

        // Issue: 4 h-chunk groups (32 KB each) + xg[t+1] prefetch group.
#pragma unroll
        for (int c = 0; c < 4; ++c) {
            const float* gsrc = hsrc + c * (128 * Bn);
            float*       sdst = sH   + c * (128 * Bn);
#pragma unroll
            for (int j = 0; j < 8; ++j) {
                const int i = tid + j * NTHR;       // 2048 16B segs / chunk
                cp_async16(sdst + i * 4, gsrc + i * 4);
            }
            CP_COMMIT();
        }
        {
            const int tn = (t + 1 < Tn) ? t + 1 : t;
            const int r = tid >> 4, seg = tid & 15;
            const int g = r >> 2, h2 = r & 3;
            const float* src = g_xg + (size_t)tn * (G4 * Bn)
                             + (size_t)(g * Hn + hrow + h2) * Bn + seg * 4;
            cp_async16(xgNxt + r * 64 + seg * 4, src);
            CP_COMMIT();
        }

        unsigned long long acc_if = 0ull, acc_go = 0ull;   // {0f,0f} packed

        // Pipelined dot: wait chunk c (+ xg[t] on c=0), then FFMA2 over it.
#pragma unroll
        for (int c = 0; c < 4; ++c) {
            if (c == 0)      { CP_WAIT(4); }   // retires xg[t] + chunk0
            else if (c == 1) { CP_WAIT(3); }
            else if (c == 2) { CP_WAIT(2); }
            else             { CP_WAIT(1); }   // leaves xg[t+1] pending
            __syncthreads();

            const float* pH = sH + c * (128 * Bn) + b;
            const float* pW = sW + c * (128 * 16) + hh * 4;
#pragma unroll 8
            for (int k = 0; k < 128; ++k) {
                const float hk = pH[k * Bn];                        // coalesced
                unsigned long long hkk;
                asm("mov.b64 %0, {%1, %1};" : "=l"(hkk) : "f"(hk)); // {hk,hk}
                const ulonglong2 w =
                    *reinterpret_cast<const ulonglong2*>(pW + k * 16); // bcast
                acc_if = ffma2(w.x, hkk, acc_if);   // {i,f}
                acc_go = ffma2(w.y, hkk, acc_go);   // {g,o}
            }
        }

        // Epilogue: fully register-local (gate order i,f,g,o).
        {
            float ai, af, ag, ao;
            asm("mov.b64 {%0, %1}, %2;" : "=f"(ai), "=f"(af) : "l"(acc_if));
            asm("mov.b64 {%0, %1}, %2;" : "=f"(ag), "=f"(ao) : "l"(acc_go));
            const float gi = xgCur[(0 * 4 + hh) * 64 + b] + ai;
            const float gf = xgCur[(1 * 4 + hh) * 64 + b] + af;
            const float gg = xgCur[(2 * 4 + hh) * 64 + b] + ag;
            const float go = xgCur[(3 * 4 + hh) * 64 + b] + ao;
            const float is = sigf(gi);
            const float fs = sigf(gf);
            const float gt = tanhf_fast(gg);
            const float os = sigf(go);
            c_state = fs * c_state + is * gt;
            const float h = os * tanhf_fast(c_state);
            hdst[(hrow + hh) * Bn + b] = h;
            if (t < mylen) maxv = fmaxf(maxv, h);
        }
        grid_barrier();   // release-arrive orders the h store
    }

    g_feat[(hrow + hh) * Bn + b] = maxv;
}

// ---------------------------------------------------------------------------
// Kernel 3: classifier  out[b][c] = sum_h feat[h][b] * W_cls[c][h] + b_cls[c]
// ---------------------------------------------------------------------------
__global__ void cls_kernel(const float* __restrict__ Wcls,
                           const float* __restrict__ bcls,
                           float* __restrict__ out) {
    const int tid = threadIdx.x;   // 128 threads
    const int b = tid >> 1, c = tid & 1;
    float s = bcls[c];
#pragma unroll 8
    for (int h = 0; h < Hn; ++h)
        s += g_feat[h * Bn + b] * Wcls[c * Hn + h];
    out[b * 2 + c] = s;
}

// ---------------------------------------------------------------------------
extern "C" void kernel_launch(void* const* d_in, const int* in_sizes, int n_in,
                              void* d_out, int out_size) {
    const int*   x      = (const int*)  d_in[0];  // [64,512] int32
    const int*   length = (const int*)  d_in[1];  // [64,1]   int32
    const float* emb    = (const float*)d_in[2];  // [32000,256]
    const float* Wih    = (const float*)d_in[3];  // [2048,256]
    const float* Whh    = (const float*)d_in[4];  // [2048,512]
    const float* bih    = (const float*)d_in[5];  // [2048]
    const float* bhh    = (const float*)d_in[6];  // [2048]
    const float* Wcls   = (const float*)d_in[7];  // [2,512]
    const float* bcls   = (const float*)d_in[8];  // [2]
    float* out = (float*)d_out;                   // [64,2]

    cudaFuncSetAttribute(lstm_kernel,
                         cudaFuncAttributeMaxDynamicSharedMemorySize, LSTM_SMEM);

    embed_gemm_kernel<<<dim3(16, Tn), 256>>>(x, emb, Wih, bih, bhh);
    lstm_kernel<<<NBLK, NTHR, LSTM_SMEM>>>(Whh, length);
    cls_kernel<<<1, 128>>>(Wcls, bcls, out);
    (void)in_sizes; (void)n_in; (void)out_size;
}